// round 6
// baseline (speedup 1.0000x reference)
#include <cuda_runtime.h>
#include <math.h>

// Problem constants
#define BH     64
#define MQ     1024
#define DH     64
#define SPAN   1024
#define KTOT   (MQ + SPAN)
#define BR     64          // query rows per block
#define BC     64          // keys per chunk
#define NCHUNK 17          // ceil((BR-1 + SPAN)/BC) = 17 chunks cover the band
#define LDS_   68          // padded smem row stride (floats), 272B = 16B aligned
#define SCALEF 0.04419417382415922f   // 1/sqrt(512)

#define SMEM_FLOATS (5 * 64 * LDS_ + 64 * 128)
#define SMEM_BYTES  (SMEM_FLOATS * 4)

__global__ __launch_bounds__(256)
void seqattn_kernel(const float* __restrict__ q,
                    const float* __restrict__ kk,
                    const float* __restrict__ vv,
                    const float* __restrict__ pe,
                    const float* __restrict__ cval,
                    float* __restrict__ out)
{
    extern __shared__ float sm[];
    float* Qs   = sm;                   // [d][r]  64 x 68
    float* Ks   = Qs  + 64 * LDS_;      // [d][j]  64 x 68
    float* PEs  = Ks  + 64 * LDS_;      // [d][jl] 64 x 68
    float* Vs   = PEs + 64 * LDS_;      // [j][d]  64 x 68
    float* Ps   = Vs  + 64 * LDS_;      // [r][j]  64 x 68
    float* POSs = Ps  + 64 * LDS_;      // [r][2*64] ring of pos l-chunks

    const int bh = blockIdx.y;
    const int m0 = blockIdx.x * BR;
    const int tid = threadIdx.x;
    const int tx = tid & 15, ty = tid >> 4;
    const int tx4 = tx * 4,  ty4 = ty * 4;

    const float cvL = cval[bh & 7] * (float)SPAN;   // current_val[head] * SPAN

    const float* qb = q  + (size_t)bh * MQ   * DH;
    const float* kb = kk + (size_t)bh * KTOT * DH;
    const float* vb = vv + (size_t)bh * KTOT * DH;

    // ---- load Q tile, transposed to [d][r] ----
    #pragma unroll
    for (int t = 0; t < 16; t++) {
        int idx = tid + t * 256;
        int r = idx >> 6, d = idx & 63;
        Qs[d * LDS_ + r] = qb[(m0 + r) * DH + d];
    }

    float mrow[4], Zrow[4], Zm[4], O[4][4];
    #pragma unroll
    for (int i = 0; i < 4; i++) {
        mrow[i] = -INFINITY; Zrow[i] = 0.f; Zm[i] = 0.f;
        #pragma unroll
        for (int k = 0; k < 4; k++) O[i][k] = 0.f;
    }

    #pragma unroll 1
    for (int c = 0; c < NCHUNK; c++) {
        const int n0 = m0 + c * BC;       // absolute key row of this chunk
        const int l0 = c * BC;            // pos l-chunk computed this iteration

        __syncthreads();   // S0: previous iteration fully consumed smem

        // ---- load K chunk transposed [d][j] ----
        #pragma unroll
        for (int t = 0; t < 16; t++) {
            int idx = tid + t * 256;
            int jr = idx >> 6, d = idx & 63;
            Ks[d * LDS_ + jr] = kb[(n0 + jr) * DH + d];
        }
        // ---- load V chunk natural [j][d] (float4) ----
        #pragma unroll
        for (int t = 0; t < 4; t++) {
            int idx4 = tid + t * 256;
            int jr = idx4 >> 4, d4 = (idx4 & 15) * 4;
            *(float4*)&Vs[jr * LDS_ + d4] = *(const float4*)&vb[(n0 + jr) * DH + d4];
        }
        // ---- load PE l-chunk [d][jl] (zero past SPAN) ----
        #pragma unroll
        for (int t = 0; t < 16; t++) {
            int idx = tid + t * 256;
            int d = idx >> 6, jl = idx & 63;
            int l = l0 + jl;
            PEs[d * LDS_ + jl] = (l < SPAN) ? pe[d * SPAN + l] : 0.f;
        }
        __syncthreads();   // S1: tiles ready

        // ---- fused GEMMs: content S = Q·K^T  and  POS chunk = Q·PE ----
        float cc[4][4], cp[4][4];
        #pragma unroll
        for (int i = 0; i < 4; i++)
            #pragma unroll
            for (int k = 0; k < 4; k++) { cc[i][k] = 0.f; cp[i][k] = 0.f; }

        #pragma unroll
        for (int d = 0; d < 64; d++) {
            float4 a  = *(float4*)&Qs [d * LDS_ + ty4];
            float4 bk = *(float4*)&Ks [d * LDS_ + tx4];
            float4 bp = *(float4*)&PEs[d * LDS_ + tx4];
            float av[4]  = {a.x,  a.y,  a.z,  a.w };
            float bkv[4] = {bk.x, bk.y, bk.z, bk.w};
            float bpv[4] = {bp.x, bp.y, bp.z, bp.w};
            #pragma unroll
            for (int i = 0; i < 4; i++)
                #pragma unroll
                for (int k = 0; k < 4; k++) {
                    cc[i][k] = fmaf(av[i], bkv[k], cc[i][k]);
                    cp[i][k] = fmaf(av[i], bpv[k], cp[i][k]);
                }
        }
        // stash POS l-chunk c into ring slot (c & 1)
        {
            int slot = (c & 1) * 64;
            #pragma unroll
            for (int i = 0; i < 4; i++)
                *(float4*)&POSs[(ty4 + i) * 128 + slot + tx4] =
                    make_float4(cp[i][0], cp[i][1], cp[i][2], cp[i][3]);
        }
        __syncthreads();   // S2: POS ring updated (chunks c-1, c now resident)

        // ---- score assembly + online softmax (per row i) ----
        #pragma unroll
        for (int i = 0; i < 4; i++) {
            int r = ty4 + i;
            float s[4], mk[4];
            float smax = -INFINITY;
            #pragma unroll
            for (int k = 0; k < 4; k++) {
                int l = l0 + tx4 + k - r;       // relative offset for this score
                if (l >= 0 && l < SPAN) {
                    float pos = POSs[r * 128 + ((l >> 6) & 1) * 64 + (l & 63)];
                    s[k] = (cc[i][k] + pos) * SCALEF;
                    float mv = ((float)(l - (SPAN - 1)) + cvL) * (1.f / 32.f) + 1.f;
                    mk[k] = fminf(fmaxf(mv, 0.f), 1.f);
                } else {
                    s[k] = -INFINITY; mk[k] = 0.f;
                }
                smax = fmaxf(smax, s[k]);
            }
            #pragma unroll
            for (int o = 8; o; o >>= 1)
                smax = fmaxf(smax, __shfl_xor_sync(0xffffffffu, smax, o, 16));
            float mnew  = fmaxf(mrow[i], smax);
            float alpha = __expf(mrow[i] - mnew);
            mrow[i] = mnew;

            float zs = 0.f, zms = 0.f, p[4];
            #pragma unroll
            for (int k = 0; k < 4; k++) {
                float e = __expf(s[k] - mnew);
                zs += e;
                float pm = e * mk[k];
                zms += pm;
                p[k] = pm;
            }
            #pragma unroll
            for (int o = 8; o; o >>= 1) {
                zs  += __shfl_xor_sync(0xffffffffu, zs,  o, 16);
                zms += __shfl_xor_sync(0xffffffffu, zms, o, 16);
            }
            Zrow[i] = Zrow[i] * alpha + zs;
            Zm[i]   = Zm[i]   * alpha + zms;
            #pragma unroll
            for (int k = 0; k < 4; k++) O[i][k] *= alpha;

            *(float4*)&Ps[r * LDS_ + tx4] = make_float4(p[0], p[1], p[2], p[3]);
        }
        __syncthreads();   // S3: P tile ready

        // ---- O += P · V ----
        #pragma unroll
        for (int j4 = 0; j4 < 64; j4 += 4) {
            float4 a0 = *(float4*)&Ps[(ty4 + 0) * LDS_ + j4];
            float4 a1 = *(float4*)&Ps[(ty4 + 1) * LDS_ + j4];
            float4 a2 = *(float4*)&Ps[(ty4 + 2) * LDS_ + j4];
            float4 a3 = *(float4*)&Ps[(ty4 + 3) * LDS_ + j4];
            float aa[4][4] = {{a0.x,a0.y,a0.z,a0.w},
                              {a1.x,a1.y,a1.z,a1.w},
                              {a2.x,a2.y,a2.z,a2.w},
                              {a3.x,a3.y,a3.z,a3.w}};
            #pragma unroll
            for (int jj = 0; jj < 4; jj++) {
                float4 b = *(float4*)&Vs[(j4 + jj) * LDS_ + tx4];
                float bv[4] = {b.x, b.y, b.z, b.w};
                #pragma unroll
                for (int i = 0; i < 4; i++)
                    #pragma unroll
                    for (int k = 0; k < 4; k++)
                        O[i][k] = fmaf(aa[i][jj], bv[k], O[i][k]);
            }
        }
    }

    // ---- epilogue: renormalize by (Zm + 1e-8 * Z) and store ----
    #pragma unroll
    for (int i = 0; i < 4; i++) {
        int r = ty4 + i;
        float den = Zm[i] + 1e-8f * Zrow[i];
        float inv = 1.f / den;
        float4 o4 = make_float4(O[i][0] * inv, O[i][1] * inv,
                                O[i][2] * inv, O[i][3] * inv);
        *(float4*)&out[((size_t)bh * MQ + m0 + r) * DH + tx4] = o4;
    }
}

extern "C" void kernel_launch(void* const* d_in, const int* in_sizes, int n_in,
                              void* d_out, int out_size)
{
    (void)in_sizes; (void)n_in; (void)out_size;
    const float* q  = (const float*)d_in[0];
    const float* k  = (const float*)d_in[1];
    const float* v  = (const float*)d_in[2];
    const float* pe = (const float*)d_in[3];
    const float* cv = (const float*)d_in[4];
    float* out = (float*)d_out;

    cudaFuncSetAttribute(seqattn_kernel,
                         cudaFuncAttributeMaxDynamicSharedMemorySize, SMEM_BYTES);

    dim3 grid(MQ / BR, BH);   // 16 x 64 = 1024 blocks
    seqattn_kernel<<<grid, 256, SMEM_BYTES>>>(q, k, v, pe, cv, out);
}

// round 7
// speedup vs baseline: 1.3480x; 1.3480x over previous
#include <cuda_runtime.h>
#include <math.h>

// Problem constants
#define BH     64
#define MQ     1024
#define DH     64
#define SPAN   1024
#define KTOT   (MQ + SPAN)
#define BR     64          // query rows per block
#define BC     64          // keys per chunk
#define NCHUNK 17          // chunks covering the 1087-wide band
#define SCALEF 0.04419417382415922f   // 1/sqrt(512)

// smem: Qs,Ks,PEs,Vs,Ps = 5 x 64x64 floats, POSs = 64x128 floats
#define SMEM_FLOATS (5*64*64 + 64*128)
#define SMEM_BYTES  (SMEM_FLOATS * 4)   // 114,688 B -> 2 blocks/SM

typedef unsigned long long u64;

__device__ __forceinline__ u64 dup2(float x) {
    u64 r; asm("mov.b64 %0, {%1, %1};" : "=l"(r) : "f"(x)); return r;
}
__device__ __forceinline__ void ffma2(u64 &d, u64 a, u64 b) {
    asm("fma.rn.f32x2 %0, %1, %2, %0;" : "+l"(d) : "l"(a), "l"(b));
}
__device__ __forceinline__ float2 unpk(u64 v) {
    float2 f; asm("mov.b64 {%0, %1}, %2;" : "=f"(f.x), "=f"(f.y) : "l"(v)); return f;
}

__global__ __launch_bounds__(256, 2)
void seqattn_kernel(const float* __restrict__ q,
                    const float* __restrict__ kk,
                    const float* __restrict__ vv,
                    const float* __restrict__ pe,
                    const float* __restrict__ cval,
                    float* __restrict__ out)
{
    extern __shared__ float sm[];
    float* Qs   = sm;              // [d][r ^ sw(d)]  64x64
    float* Ks   = Qs  + 4096;      // [d][j ^ sw(d)]  64x64
    float* PEs  = Ks  + 4096;      // [d][jl]         64x64
    float* Vs   = PEs + 4096;      // [j][d]          64x64
    float* Ps   = Vs  + 4096;      // [r][j]          64x64
    float* POSs = Ps  + 4096;      // [r][128] ring of two 64-wide pos l-chunks

    const int bh = blockIdx.y;
    const int m0 = blockIdx.x * BR;
    const int tid = threadIdx.x;
    const int tx = tid & 15, ty = tid >> 4;
    const int tx4 = tx * 4,  ty4 = ty * 4;

    const float cvL = cval[bh & 7] * (float)SPAN;

    const float* qb = q  + (size_t)bh * MQ   * DH;
    const float* kb = kk + (size_t)bh * KTOT * DH;
    const float* vb = vv + (size_t)bh * KTOT * DH;

    // ---- load Q tile: float4 LDG, transposed + XOR-swizzled scalar STS ----
    #pragma unroll
    for (int t = 0; t < 4; t++) {
        int idx = tid + t * 256;               // 1024 float4 groups
        int r = idx >> 4, d4 = (idx & 15) * 4;
        float4 v = *(const float4*)&qb[(m0 + r) * DH + d4];
        float vv4[4] = {v.x, v.y, v.z, v.w};
        #pragma unroll
        for (int x = 0; x < 4; x++) {
            int d = d4 + x;
            Qs[d * 64 + (r ^ ((d & 15) << 2))] = vv4[x];
        }
    }

    float Zr[4] = {0.f, 0.f, 0.f, 0.f};
    float Zm[4] = {0.f, 0.f, 0.f, 0.f};
    u64 O2[4][2];
    #pragma unroll
    for (int i = 0; i < 4; i++) { O2[i][0] = 0ull; O2[i][1] = 0ull; }

    #pragma unroll 1
    for (int c = 0; c < NCHUNK; c++) {
        const int n0 = m0 + c * BC;
        const int l0 = c * BC;

        __syncthreads();   // S0: previous chunk fully consumed smem

        // ---- K chunk: float4 LDG, transposed + swizzled STS ----
        #pragma unroll
        for (int t = 0; t < 4; t++) {
            int idx = tid + t * 256;
            int jr = idx >> 4, d4 = (idx & 15) * 4;
            float4 v = *(const float4*)&kb[(n0 + jr) * DH + d4];
            float vv4[4] = {v.x, v.y, v.z, v.w};
            #pragma unroll
            for (int x = 0; x < 4; x++) {
                int d = d4 + x;
                Ks[d * 64 + (jr ^ ((d & 15) << 2))] = vv4[x];
            }
        }
        // ---- V chunk natural [j][d], float4 ----
        #pragma unroll
        for (int t = 0; t < 4; t++) {
            int idx = tid + t * 256;
            int jr = idx >> 4, d4 = (idx & 15) * 4;
            *(float4*)&Vs[jr * 64 + d4] = *(const float4*)&vb[(n0 + jr) * DH + d4];
        }
        // ---- PE l-chunk [d][jl], float4 (chunk is wholly in or out of SPAN) ----
        if (l0 < SPAN) {
            #pragma unroll
            for (int t = 0; t < 4; t++) {
                int idx = tid + t * 256;
                int d = idx >> 4, j4 = (idx & 15) * 4;
                *(float4*)&PEs[d * 64 + j4] = *(const float4*)&pe[d * SPAN + l0 + j4];
            }
        } else {
            float4 z = make_float4(0.f, 0.f, 0.f, 0.f);
            #pragma unroll
            for (int t = 0; t < 4; t++) {
                int idx = tid + t * 256;
                int d = idx >> 4, j4 = (idx & 15) * 4;
                *(float4*)&PEs[d * 64 + j4] = z;
            }
        }
        __syncthreads();   // S1: tiles ready

        // ---- fused GEMMs (packed f32x2): content S = Q.K^T, POS chunk = Q.PE ----
        u64 cc2[4][2], cp2[4][2];
        #pragma unroll
        for (int i = 0; i < 4; i++) {
            cc2[i][0] = 0ull; cc2[i][1] = 0ull;
            cp2[i][0] = 0ull; cp2[i][1] = 0ull;
        }

        #pragma unroll
        for (int d = 0; d < 64; d++) {
            int sw = (d & 15) << 2;
            float4 a      = *(float4*)    &Qs [d * 64 + (ty4 ^ sw)];
            ulonglong2 bk = *(ulonglong2*)&Ks [d * 64 + (tx4 ^ sw)];
            ulonglong2 bp = *(ulonglong2*)&PEs[d * 64 + tx4];
            u64 ad[4] = {dup2(a.x), dup2(a.y), dup2(a.z), dup2(a.w)};
            #pragma unroll
            for (int i = 0; i < 4; i++) {
                ffma2(cc2[i][0], ad[i], bk.x);
                ffma2(cc2[i][1], ad[i], bk.y);
                ffma2(cp2[i][0], ad[i], bp.x);
                ffma2(cp2[i][1], ad[i], bp.y);
            }
        }

        // stash POS l-chunk c into ring slot (c & 1) — within-warp producer/consumer
        {
            int slot = (c & 1) * 64;
            #pragma unroll
            for (int i = 0; i < 4; i++) {
                ulonglong2 w; w.x = cp2[i][0]; w.y = cp2[i][1];
                *(ulonglong2*)&POSs[(ty4 + i) * 128 + slot + tx4] = w;
            }
        }
        __syncwarp();      // ring rows are ty-partitioned -> warp-local sync suffices

        // ---- score assembly + masked exp, deferred normalization ----
        #pragma unroll
        for (int i = 0; i < 4; i++) {
            int r = ty4 + i;
            float2 c0 = unpk(cc2[i][0]), c1 = unpk(cc2[i][1]);
            float ccf[4] = {c0.x, c0.y, c1.x, c1.y};
            float p[4];
            float zs = 0.f, zms = 0.f;
            #pragma unroll
            for (int k = 0; k < 4; k++) {
                int l = l0 + tx4 + k - r;
                bool ok = ((unsigned)l < (unsigned)SPAN);
                float pos = POSs[r * 128 + (l & 127)];   // safe addr even when !ok
                float e = __expf((ccf[k] + pos) * SCALEF);
                e = ok ? e : 0.f;
                float mv = ((float)(l - (SPAN - 1)) + cvL) * (1.f / 32.f) + 1.f;
                float mk = fminf(fmaxf(mv, 0.f), 1.f);
                float pm = e * mk;
                zs += e; zms += pm;
                p[k] = pm;
            }
            Zr[i] += zs;
            Zm[i] += zms;
            *(float4*)&Ps[r * 64 + tx4] = make_float4(p[0], p[1], p[2], p[3]);
        }
        __syncwarp();      // P rows are ty-partitioned -> warp-local sync suffices

        // ---- O += P . V  (packed f32x2) ----
        #pragma unroll
        for (int j4 = 0; j4 < 64; j4 += 4) {
            float4 a0 = *(float4*)&Ps[(ty4 + 0) * 64 + j4];
            float4 a1 = *(float4*)&Ps[(ty4 + 1) * 64 + j4];
            float4 a2 = *(float4*)&Ps[(ty4 + 2) * 64 + j4];
            float4 a3 = *(float4*)&Ps[(ty4 + 3) * 64 + j4];
            float aa[4][4] = {{a0.x,a0.y,a0.z,a0.w},
                              {a1.x,a1.y,a1.z,a1.w},
                              {a2.x,a2.y,a2.z,a2.w},
                              {a3.x,a3.y,a3.z,a3.w}};
            #pragma unroll
            for (int jj = 0; jj < 4; jj++) {
                ulonglong2 b = *(ulonglong2*)&Vs[(j4 + jj) * 64 + tx4];
                #pragma unroll
                for (int i = 0; i < 4; i++) {
                    u64 ad = dup2(aa[i][jj]);
                    ffma2(O2[i][0], ad, b.x);
                    ffma2(O2[i][1], ad, b.y);
                }
            }
        }
    }

    // ---- epilogue: single cross-thread reduction + renormalize + store ----
    #pragma unroll
    for (int i = 0; i < 4; i++) {
        float zr = Zr[i], zm = Zm[i];
        #pragma unroll
        for (int o = 8; o; o >>= 1) {
            zr += __shfl_xor_sync(0xffffffffu, zr, o, 16);
            zm += __shfl_xor_sync(0xffffffffu, zm, o, 16);
        }
        float inv = 1.f / (zm + 1e-8f * zr);
        float2 oa = unpk(O2[i][0]), ob = unpk(O2[i][1]);
        *(float4*)&out[((size_t)bh * MQ + m0 + ty4 + i) * DH + tx4] =
            make_float4(oa.x * inv, oa.y * inv, ob.x * inv, ob.y * inv);
    }
}

extern "C" void kernel_launch(void* const* d_in, const int* in_sizes, int n_in,
                              void* d_out, int out_size)
{
    (void)in_sizes; (void)n_in; (void)out_size;
    const float* q  = (const float*)d_in[0];
    const float* k  = (const float*)d_in[1];
    const float* v  = (const float*)d_in[2];
    const float* pe = (const float*)d_in[3];
    const float* cv = (const float*)d_in[4];
    float* out = (float*)d_out;

    cudaFuncSetAttribute(seqattn_kernel,
                         cudaFuncAttributeMaxDynamicSharedMemorySize, SMEM_BYTES);

    dim3 grid(MQ / BR, BH);   // 16 x 64 = 1024 blocks
    seqattn_kernel<<<grid, 256, SMEM_BYTES>>>(q, k, v, pe, cv, out);
}

// round 8
// speedup vs baseline: 1.3488x; 1.0006x over previous
#include <cuda_runtime.h>
#include <math.h>

// Problem constants
#define BH     64
#define MQ     1024
#define DH     64
#define SPAN   1024
#define KTOT   (MQ + SPAN)
#define BR     64          // query rows per block
#define BC     64          // keys per chunk
#define NCHUNK 17          // chunks covering the 1087-wide band
#define SCALEF 0.04419417382415922f   // 1/sqrt(512)

// smem: Qs,Ks,PEs,Vs,Ps = 5 x 64x64 floats, POSs = 64x128 floats
#define SMEM_FLOATS (5*64*64 + 64*128)
#define SMEM_BYTES  (SMEM_FLOATS * 4)   // 114,688 B -> 2 blocks/SM

typedef unsigned long long u64;

__device__ __forceinline__ u64 dup2(float x) {
    u64 r; asm("mov.b64 %0, {%1, %1};" : "=l"(r) : "f"(x)); return r;
}
__device__ __forceinline__ void ffma2(u64 &d, u64 a, u64 b) {
    asm("fma.rn.f32x2 %0, %1, %2, %0;" : "+l"(d) : "l"(a), "l"(b));
}
__device__ __forceinline__ float2 unpk(u64 v) {
    float2 f; asm("mov.b64 {%0, %1}, %2;" : "=f"(f.x), "=f"(f.y) : "l"(v)); return f;
}

__global__ __launch_bounds__(256, 2)
void seqattn_kernel(const float* __restrict__ q,
                    const float* __restrict__ kk,
                    const float* __restrict__ vv,
                    const float* __restrict__ pe,
                    const float* __restrict__ cval,
                    float* __restrict__ out)
{
    extern __shared__ float sm[];
    float* Qs   = sm;              // [d][r ^ sw(d)]  64x64
    float* Ks   = Qs  + 4096;      // [d][j ^ sw(d)]  64x64
    float* PEs  = Ks  + 4096;      // [d][jl]         64x64
    float* Vs   = PEs + 4096;      // [j][d]          64x64
    float* Ps   = Vs  + 4096;      // [r][j]          64x64
    float* POSs = Ps  + 4096;      // [r][128] ring of two 64-wide pos l-chunks

    const int bh = blockIdx.y;
    const int m0 = blockIdx.x * BR;
    const int tid = threadIdx.x;
    const int tx = tid & 15, ty = tid >> 4;
    const int tx4 = tx * 4,  ty4 = ty * 4;

    const float cvL = cval[bh & 7] * (float)SPAN;

    const float* qb = q  + (size_t)bh * MQ   * DH;
    const float* kb = kk + (size_t)bh * KTOT * DH;
    const float* vb = vv + (size_t)bh * KTOT * DH;

    // ---- load Q tile: float4 LDG, transposed + XOR-swizzled scalar STS ----
    #pragma unroll
    for (int t = 0; t < 4; t++) {
        int idx = tid + t * 256;               // 1024 float4 groups
        int r = idx >> 4, d4 = (idx & 15) * 4;
        float4 v = *(const float4*)&qb[(m0 + r) * DH + d4];
        float vv4[4] = {v.x, v.y, v.z, v.w};
        #pragma unroll
        for (int x = 0; x < 4; x++) {
            int d = d4 + x;
            Qs[d * 64 + (r ^ ((d & 15) << 2))] = vv4[x];
        }
    }

    float Zr[4] = {0.f, 0.f, 0.f, 0.f};
    float Zm[4] = {0.f, 0.f, 0.f, 0.f};
    u64 O2[4][2];
    #pragma unroll
    for (int i = 0; i < 4; i++) { O2[i][0] = 0ull; O2[i][1] = 0ull; }

    #pragma unroll 1
    for (int c = 0; c < NCHUNK; c++) {
        const int n0 = m0 + c * BC;
        const int l0 = c * BC;

        __syncthreads();   // S0: previous chunk fully consumed smem

        // ---- K chunk: float4 LDG, transposed + swizzled STS ----
        #pragma unroll
        for (int t = 0; t < 4; t++) {
            int idx = tid + t * 256;
            int jr = idx >> 4, d4 = (idx & 15) * 4;
            float4 v = *(const float4*)&kb[(n0 + jr) * DH + d4];
            float vv4[4] = {v.x, v.y, v.z, v.w};
            #pragma unroll
            for (int x = 0; x < 4; x++) {
                int d = d4 + x;
                Ks[d * 64 + (jr ^ ((d & 15) << 2))] = vv4[x];
            }
        }
        // ---- V chunk natural [j][d], float4 ----
        #pragma unroll
        for (int t = 0; t < 4; t++) {
            int idx = tid + t * 256;
            int jr = idx >> 4, d4 = (idx & 15) * 4;
            *(float4*)&Vs[jr * 64 + d4] = *(const float4*)&vb[(n0 + jr) * DH + d4];
        }
        // ---- PE l-chunk [d][jl], float4 (chunk is wholly in or out of SPAN) ----
        if (l0 < SPAN) {
            #pragma unroll
            for (int t = 0; t < 4; t++) {
                int idx = tid + t * 256;
                int d = idx >> 4, j4 = (idx & 15) * 4;
                *(float4*)&PEs[d * 64 + j4] = *(const float4*)&pe[d * SPAN + l0 + j4];
            }
        } else {
            float4 z = make_float4(0.f, 0.f, 0.f, 0.f);
            #pragma unroll
            for (int t = 0; t < 4; t++) {
                int idx = tid + t * 256;
                int d = idx >> 4, j4 = (idx & 15) * 4;
                *(float4*)&PEs[d * 64 + j4] = z;
            }
        }
        __syncthreads();   // S1: tiles ready

        // ---- fused GEMMs (packed f32x2): content S = Q.K^T, POS chunk = Q.PE ----
        u64 cc2[4][2], cp2[4][2];
        #pragma unroll
        for (int i = 0; i < 4; i++) {
            cc2[i][0] = 0ull; cc2[i][1] = 0ull;
            cp2[i][0] = 0ull; cp2[i][1] = 0ull;
        }

        #pragma unroll
        for (int d = 0; d < 64; d++) {
            int sw = (d & 15) << 2;
            float4 a      = *(float4*)    &Qs [d * 64 + (ty4 ^ sw)];
            ulonglong2 bk = *(ulonglong2*)&Ks [d * 64 + (tx4 ^ sw)];
            ulonglong2 bp = *(ulonglong2*)&PEs[d * 64 + tx4];
            u64 ad[4] = {dup2(a.x), dup2(a.y), dup2(a.z), dup2(a.w)};
            #pragma unroll
            for (int i = 0; i < 4; i++) {
                ffma2(cc2[i][0], ad[i], bk.x);
                ffma2(cc2[i][1], ad[i], bk.y);
                ffma2(cp2[i][0], ad[i], bp.x);
                ffma2(cp2[i][1], ad[i], bp.y);
            }
        }

        // stash POS l-chunk c into ring slot (c & 1) — within-warp producer/consumer
        {
            int slot = (c & 1) * 64;
            #pragma unroll
            for (int i = 0; i < 4; i++) {
                ulonglong2 w; w.x = cp2[i][0]; w.y = cp2[i][1];
                *(ulonglong2*)&POSs[(ty4 + i) * 128 + slot + tx4] = w;
            }
        }
        __syncwarp();      // ring rows are ty-partitioned -> warp-local sync suffices

        // ---- score assembly + masked exp, deferred normalization ----
        #pragma unroll
        for (int i = 0; i < 4; i++) {
            int r = ty4 + i;
            float2 c0 = unpk(cc2[i][0]), c1 = unpk(cc2[i][1]);
            float ccf[4] = {c0.x, c0.y, c1.x, c1.y};
            float p[4];
            float zs = 0.f, zms = 0.f;
            #pragma unroll
            for (int k = 0; k < 4; k++) {
                int l = l0 + tx4 + k - r;
                bool ok = ((unsigned)l < (unsigned)SPAN);
                float pos = POSs[r * 128 + (l & 127)];   // safe addr even when !ok
                float e = __expf((ccf[k] + pos) * SCALEF);
                e = ok ? e : 0.f;
                float mv = ((float)(l - (SPAN - 1)) + cvL) * (1.f / 32.f) + 1.f;
                float mk = fminf(fmaxf(mv, 0.f), 1.f);
                float pm = e * mk;
                zs += e; zms += pm;
                p[k] = pm;
            }
            Zr[i] += zs;
            Zm[i] += zms;
            *(float4*)&Ps[r * 64 + tx4] = make_float4(p[0], p[1], p[2], p[3]);
        }
        __syncwarp();      // P rows are ty-partitioned -> warp-local sync suffices

        // ---- O += P . V  (packed f32x2) ----
        #pragma unroll
        for (int j4 = 0; j4 < 64; j4 += 4) {
            float4 a0 = *(float4*)&Ps[(ty4 + 0) * 64 + j4];
            float4 a1 = *(float4*)&Ps[(ty4 + 1) * 64 + j4];
            float4 a2 = *(float4*)&Ps[(ty4 + 2) * 64 + j4];
            float4 a3 = *(float4*)&Ps[(ty4 + 3) * 64 + j4];
            float aa[4][4] = {{a0.x,a0.y,a0.z,a0.w},
                              {a1.x,a1.y,a1.z,a1.w},
                              {a2.x,a2.y,a2.z,a2.w},
                              {a3.x,a3.y,a3.z,a3.w}};
            #pragma unroll
            for (int jj = 0; jj < 4; jj++) {
                ulonglong2 b = *(ulonglong2*)&Vs[(j4 + jj) * 64 + tx4];
                #pragma unroll
                for (int i = 0; i < 4; i++) {
                    u64 ad = dup2(aa[i][jj]);
                    ffma2(O2[i][0], ad, b.x);
                    ffma2(O2[i][1], ad, b.y);
                }
            }
        }
    }

    // ---- epilogue: single cross-thread reduction + renormalize + store ----
    #pragma unroll
    for (int i = 0; i < 4; i++) {
        float zr = Zr[i], zm = Zm[i];
        #pragma unroll
        for (int o = 8; o; o >>= 1) {
            zr += __shfl_xor_sync(0xffffffffu, zr, o, 16);
            zm += __shfl_xor_sync(0xffffffffu, zm, o, 16);
        }
        float inv = 1.f / (zm + 1e-8f * zr);
        float2 oa = unpk(O2[i][0]), ob = unpk(O2[i][1]);
        *(float4*)&out[((size_t)bh * MQ + m0 + ty4 + i) * DH + tx4] =
            make_float4(oa.x * inv, oa.y * inv, ob.x * inv, ob.y * inv);
    }
}

extern "C" void kernel_launch(void* const* d_in, const int* in_sizes, int n_in,
                              void* d_out, int out_size)
{
    (void)in_sizes; (void)n_in; (void)out_size;
    const float* q  = (const float*)d_in[0];
    const float* k  = (const float*)d_in[1];
    const float* v  = (const float*)d_in[2];
    const float* pe = (const float*)d_in[3];
    const float* cv = (const float*)d_in[4];
    float* out = (float*)d_out;

    cudaFuncSetAttribute(seqattn_kernel,
                         cudaFuncAttributeMaxDynamicSharedMemorySize, SMEM_BYTES);

    dim3 grid(MQ / BR, BH);   // 16 x 64 = 1024 blocks
    seqattn_kernel<<<grid, 256, SMEM_BYTES>>>(q, k, v, pe, cv, out);
}

// round 10
// speedup vs baseline: 1.7317x; 1.2839x over previous
#include <cuda_runtime.h>
#include <cuda_bf16.h>
#include <stdint.h>

#define STRH 72          // bf16 elems per smem tile row (144 B)
#define CEXP 0.06375846855f   // (1/sqrt(512)) * log2(e)
#define RSTR 132         // ring row stride (f32)
#define OSTR 68          // Obuf row stride (f32)

// smem byte offsets
#define T_QH   0
#define T_QL   9216
#define T_KH   18432
#define T_KL   27648
#define T_VH   36864
#define T_VL   46080
#define T_PEH  55296
#define T_PEL  64512
#define T_RING 73728     // ring 64x132 f32 (33792 B); epilogue: 2 Obufs 64x68 f32
#define T_ZR   108544
#define T_ZM   109056
#define SMEM_TOTAL 109568

typedef uint32_t u32;

__device__ __forceinline__ u32 pkbf(float a, float b) {
    __nv_bfloat162 t = __floats2bfloat162_rn(a, b);
    return *reinterpret_cast<u32*>(&t);
}
__device__ __forceinline__ float bflo(float x) {
    return x - __bfloat162float(__float2bfloat16_rn(x));
}
__device__ __forceinline__ void mma(float* c, const u32* a, const u32* b) {
    asm volatile("mma.sync.aligned.m16n8k16.row.col.f32.bf16.bf16.f32 "
        "{%0,%1,%2,%3}, {%4,%5,%6,%7}, {%8,%9}, {%0,%1,%2,%3};"
        : "+f"(c[0]), "+f"(c[1]), "+f"(c[2]), "+f"(c[3])
        : "r"(a[0]), "r"(a[1]), "r"(a[2]), "r"(a[3]), "r"(b[0]), "r"(b[1]));
}

// 64x64 f32 gmem tile -> bf16 hi/lo smem, natural [r][d]
__device__ __forceinline__ void cvt_nat(const float* __restrict__ src,
                                        __nv_bfloat16* dh, __nv_bfloat16* dl, int tid) {
    #pragma unroll
    for (int t = 0; t < 4; t++) {
        int idx = tid + t * 256;
        int r = idx >> 4, d4 = (idx & 15) * 4;
        float4 v = *(const float4*)(src + r * 64 + d4);
        *(uint2*)(dh + r * STRH + d4) =
            make_uint2(pkbf(v.x, v.y), pkbf(v.z, v.w));
        *(uint2*)(dl + r * STRH + d4) =
            make_uint2(pkbf(bflo(v.x), bflo(v.y)), pkbf(bflo(v.z), bflo(v.w)));
    }
}

// 64x64 f32 gmem tile (row stride gs) -> TRANSPOSED bf16 hi/lo smem [col][row]
// 4x4 in-register shuffle transpose; coalesced LDG.128, conflict-free STS.32
__device__ __forceinline__ void cvt_trans(const float* __restrict__ src, int gs,
                                          __nv_bfloat16* dh, __nv_bfloat16* dl, int tid) {
    int lane = tid & 31, l4 = lane & 3, grp = tid >> 2;
    #pragma unroll
    for (int t = 0; t < 4; t++) {
        int blk = grp + t * 64;            // 256 4x4 blocks
        int jb = (blk & 15) * 4;           // gmem row block
        int db = (blk >> 4) * 4;           // gmem col block
        float4 v = *(const float4*)(src + (size_t)(jb + l4) * gs + db);
        float vv[4] = {v.x, v.y, v.z, v.w};
        float w[4];
        #pragma unroll
        for (int s = 0; s < 4; s++) {
            float sent = vv[(l4 + s) & 3];
            int sl = (lane & ~3) | ((l4 - s) & 3);
            w[(l4 - s) & 3] = __shfl_sync(0xffffffffu, sent, sl);
        }
        int dr = db + l4;                  // dest row = gmem col
        *(u32*)(dh + dr * STRH + jb)     = pkbf(w[0], w[1]);
        *(u32*)(dh + dr * STRH + jb + 2) = pkbf(w[2], w[3]);
        *(u32*)(dl + dr * STRH + jb)     = pkbf(bflo(w[0]), bflo(w[1]));
        *(u32*)(dl + dr * STRH + jb + 2) = pkbf(bflo(w[2]), bflo(w[3]));
    }
}

__global__ __launch_bounds__(256, 2)
void seqattn_mma(const float* __restrict__ q,  const float* __restrict__ kk,
                 const float* __restrict__ vv, const float* __restrict__ pe,
                 const float* __restrict__ cval, float* __restrict__ out)
{
    extern __shared__ char smem[];
    __nv_bfloat16* Qh  = (__nv_bfloat16*)(smem + T_QH);
    __nv_bfloat16* Ql  = (__nv_bfloat16*)(smem + T_QL);
    __nv_bfloat16* Kh  = (__nv_bfloat16*)(smem + T_KH);
    __nv_bfloat16* Kl  = (__nv_bfloat16*)(smem + T_KL);
    __nv_bfloat16* Vth = (__nv_bfloat16*)(smem + T_VH);
    __nv_bfloat16* Vtl = (__nv_bfloat16*)(smem + T_VL);
    __nv_bfloat16* Ph_ = (__nv_bfloat16*)(smem + T_PEH);
    __nv_bfloat16* Pl_ = (__nv_bfloat16*)(smem + T_PEL);
    float* ring = (float*)(smem + T_RING);

    const int tid = threadIdx.x;
    const int lane = tid & 31, w = tid >> 5;
    const int g = lane >> 2, tig = lane & 3;
    const int wr = w & 3, wc = w >> 2;
    const int r0 = wr * 16;          // block-local row strip base
    const int cb = wc * 32;          // col strip base

    const int bh = blockIdx.y, m0 = blockIdx.x * 64;
    const float cvL  = cval[bh & 7] * 1024.0f;
    const float madd = (cvL - 1023.0f) * 0.03125f + 1.0f;

    const float* qb = q  + (size_t)bh * 1024 * 64;
    const float* kb = kk + (size_t)bh * 2048 * 64;
    const float* vb = vv + (size_t)bh * 2048 * 64;

    cvt_nat(qb + (size_t)m0 * 64, Qh, Ql, tid);
    __syncthreads();

    // Q A-fragments, loaded once (persist across chunks)
    u32 qfh[4][4], qfl[4][4];
    #pragma unroll
    for (int kt = 0; kt < 4; kt++) {
        int co = kt * 16 + tig * 2;
        const __nv_bfloat16* ph = Qh + (r0 + g) * STRH + co;
        const __nv_bfloat16* pl = Ql + (r0 + g) * STRH + co;
        qfh[kt][0] = *(const u32*)ph;
        qfh[kt][1] = *(const u32*)(ph + 8 * STRH);
        qfh[kt][2] = *(const u32*)(ph + 8);
        qfh[kt][3] = *(const u32*)(ph + 8 * STRH + 8);
        qfl[kt][0] = *(const u32*)pl;
        qfl[kt][1] = *(const u32*)(pl + 8 * STRH);
        qfl[kt][2] = *(const u32*)(pl + 8);
        qfl[kt][3] = *(const u32*)(pl + 8 * STRH + 8);
    }

    float o[8][4];
    #pragma unroll
    for (int i = 0; i < 8; i++) { o[i][0] = o[i][1] = o[i][2] = o[i][3] = 0.f; }
    float zr0 = 0.f, zr1 = 0.f, zm0 = 0.f, zm1 = 0.f;

    #pragma unroll 1
    for (int c = 0; c < 17; c++) {
        const int n0 = m0 + c * 64, l0 = c * 64;

        __syncthreads();   // prev chunk's smem consumers done
        cvt_nat(kb + (size_t)n0 * 64, Kh, Kl, tid);
        cvt_trans(vb + (size_t)n0 * 64, 64, Vth, Vtl, tid);
        if (l0 < 1024) cvt_trans(pe + l0, 1024, Ph_, Pl_, tid);
        __syncthreads();   // tiles ready

        float cs[4][4];
        // ---- POS = Q . PE^T (skip for the all-masked last chunk) ----
        if (l0 < 1024) {
            #pragma unroll
            for (int nt = 0; nt < 4; nt++)
                cs[nt][0] = cs[nt][1] = cs[nt][2] = cs[nt][3] = 0.f;
            #pragma unroll
            for (int nt = 0; nt < 4; nt++) {
                const __nv_bfloat16* bhp = Ph_ + (cb + 8 * nt + g) * STRH + tig * 2;
                const __nv_bfloat16* blp = Pl_ + (cb + 8 * nt + g) * STRH + tig * 2;
                #pragma unroll
                for (int kt = 0; kt < 4; kt++) {
                    u32 bhf[2] = {*(const u32*)(bhp + 16 * kt), *(const u32*)(bhp + 16 * kt + 8)};
                    u32 blf[2] = {*(const u32*)(blp + 16 * kt), *(const u32*)(blp + 16 * kt + 8)};
                    mma(cs[nt], qfh[kt], bhf);
                    mma(cs[nt], qfh[kt], blf);
                    mma(cs[nt], qfl[kt], bhf);
                }
            }
            int slot = (c & 1) * 64;
            #pragma unroll
            for (int nt = 0; nt < 4; nt++) {
                int jl = cb + 8 * nt + tig * 2;
                ring[(r0 + g) * RSTR + slot + jl]         = cs[nt][0];
                ring[(r0 + g) * RSTR + slot + jl + 1]     = cs[nt][1];
                ring[(r0 + g + 8) * RSTR + slot + jl]     = cs[nt][2];
                ring[(r0 + g + 8) * RSTR + slot + jl + 1] = cs[nt][3];
            }
        }

        // ---- S = Q . K^T ----
        #pragma unroll
        for (int nt = 0; nt < 4; nt++)
            cs[nt][0] = cs[nt][1] = cs[nt][2] = cs[nt][3] = 0.f;
        #pragma unroll
        for (int nt = 0; nt < 4; nt++) {
            const __nv_bfloat16* bhp = Kh + (cb + 8 * nt + g) * STRH + tig * 2;
            const __nv_bfloat16* blp = Kl + (cb + 8 * nt + g) * STRH + tig * 2;
            #pragma unroll
            for (int kt = 0; kt < 4; kt++) {
                u32 bhf[2] = {*(const u32*)(bhp + 16 * kt), *(const u32*)(bhp + 16 * kt + 8)};
                u32 blf[2] = {*(const u32*)(blp + 16 * kt), *(const u32*)(blp + 16 * kt + 8)};
                mma(cs[nt], qfh[kt], bhf);
                mma(cs[nt], qfh[kt], blf);
                mma(cs[nt], qfl[kt], bhf);
            }
        }
        __syncthreads();   // ring slot c visible to all warps

        // ---- scoring: exp2 poly + span mask, deferred normalization (in-place into cs) ----
        #pragma unroll
        for (int nt = 0; nt < 4; nt++) {
            #pragma unroll
            for (int e = 0; e < 4; e++) {
                int rr = r0 + g + (e & 2) * 4;
                int j  = cb + 8 * nt + tig * 2 + (e & 1);
                int l  = l0 + j - rr;
                float pos = ring[rr * RSTR + (l & 127)];
                float y = (cs[nt][e] + pos) * CEXP;
                int ni = __float2int_rn(y);
                float f = y - (float)ni;
                float p = fmaf(f, 1.3333558146e-3f, 9.6181291076e-3f);
                p = fmaf(f, p, 5.5504108664e-2f);
                p = fmaf(f, p, 2.4022650696e-1f);
                p = fmaf(f, p, 6.9314718056e-1f);
                p = fmaf(f, p, 1.0f);
                float ev = __int_as_float(__float_as_int(p) + (ni << 23));
                bool ok = ((unsigned)l < 1024u);
                ev = ok ? ev : 0.f;
                float mk = fminf(fmaxf(fmaf((float)l, 0.03125f, madd), 0.f), 1.f);
                float pm = ev * mk;
                if (e & 2) { zr1 += ev; zm1 += pm; }
                else       { zr0 += ev; zm0 += pm; }
                cs[nt][e] = pm;
            }
        }

        // ---- pack P into A-fragments (register-only, FA2 trick) ----
        u32 pfh[2][4], pfl[2][4];
        #pragma unroll
        for (int k2 = 0; k2 < 2; k2++) {
            pfh[k2][0] = pkbf(cs[2*k2][0], cs[2*k2][1]);
            pfh[k2][1] = pkbf(cs[2*k2][2], cs[2*k2][3]);
            pfh[k2][2] = pkbf(cs[2*k2+1][0], cs[2*k2+1][1]);
            pfh[k2][3] = pkbf(cs[2*k2+1][2], cs[2*k2+1][3]);
            pfl[k2][0] = pkbf(bflo(cs[2*k2][0]), bflo(cs[2*k2][1]));
            pfl[k2][1] = pkbf(bflo(cs[2*k2][2]), bflo(cs[2*k2][3]));
            pfl[k2][2] = pkbf(bflo(cs[2*k2+1][0]), bflo(cs[2*k2+1][1]));
            pfl[k2][3] = pkbf(bflo(cs[2*k2+1][2]), bflo(cs[2*k2+1][3]));
        }

        // ---- O += P . V (warp's 32-key half; cross-warp halves summed at epilogue) ----
        #pragma unroll
        for (int nt = 0; nt < 8; nt++) {
            const __nv_bfloat16* bhp = Vth + (8 * nt + g) * STRH + cb + tig * 2;
            const __nv_bfloat16* blp = Vtl + (8 * nt + g) * STRH + cb + tig * 2;
            #pragma unroll
            for (int k2 = 0; k2 < 2; k2++) {
                u32 bhf[2] = {*(const u32*)(bhp + 16 * k2), *(const u32*)(bhp + 16 * k2 + 8)};
                u32 blf[2] = {*(const u32*)(blp + 16 * k2), *(const u32*)(blp + 16 * k2 + 8)};
                mma(o[nt], pfh[k2], bhf);
                mma(o[nt], pfh[k2], blf);
                mma(o[nt], pfl[k2], bhf);
            }
        }
    }

    // ---------------- epilogue ----------------
    __syncthreads();   // last chunk's ring reads done; reuse ring region as Obufs
    zr0 += __shfl_xor_sync(0xffffffffu, zr0, 1); zr0 += __shfl_xor_sync(0xffffffffu, zr0, 2);
    zr1 += __shfl_xor_sync(0xffffffffu, zr1, 1); zr1 += __shfl_xor_sync(0xffffffffu, zr1, 2);
    zm0 += __shfl_xor_sync(0xffffffffu, zm0, 1); zm0 += __shfl_xor_sync(0xffffffffu, zm0, 2);
    zm1 += __shfl_xor_sync(0xffffffffu, zm1, 1); zm1 += __shfl_xor_sync(0xffffffffu, zm1, 2);
    float* ZR = (float*)(smem + T_ZR);
    float* ZM = (float*)(smem + T_ZM);
    if (tig == 0) {
        ZR[wc * 64 + r0 + g] = zr0;  ZR[wc * 64 + r0 + g + 8] = zr1;
        ZM[wc * 64 + r0 + g] = zm0;  ZM[wc * 64 + r0 + g + 8] = zm1;
    }
    float* Ob = (float*)(smem + T_RING) + wc * (64 * OSTR);
    #pragma unroll
    for (int nt = 0; nt < 8; nt++) {
        int d = 8 * nt + tig * 2;
        Ob[(r0 + g) * OSTR + d]         = o[nt][0];
        Ob[(r0 + g) * OSTR + d + 1]     = o[nt][1];
        Ob[(r0 + g + 8) * OSTR + d]     = o[nt][2];
        Ob[(r0 + g + 8) * OSTR + d + 1] = o[nt][3];
    }
    __syncthreads();
    float* A = (float*)(smem + T_RING);
    float* B = A + 64 * OSTR;
    #pragma unroll
    for (int t = 0; t < 4; t++) {
        int idx = tid + t * 256;
        int r = idx >> 4, d4 = (idx & 15) * 4;
        float inv = 1.f / ((ZM[r] + ZM[64 + r]) + 1e-8f * (ZR[r] + ZR[64 + r]));
        float4 a = *(float4*)&A[r * OSTR + d4];
        float4 b = *(float4*)&B[r * OSTR + d4];
        float4 ov = make_float4((a.x + b.x) * inv, (a.y + b.y) * inv,
                                (a.z + b.z) * inv, (a.w + b.w) * inv);
        *(float4*)&out[((size_t)bh * 1024 + m0 + r) * 64 + d4] = ov;
    }
}

extern "C" void kernel_launch(void* const* d_in, const int* in_sizes, int n_in,
                              void* d_out, int out_size)
{
    (void)in_sizes; (void)n_in; (void)out_size;
    cudaFuncSetAttribute(seqattn_mma, cudaFuncAttributeMaxDynamicSharedMemorySize, SMEM_TOTAL);
    dim3 grid(16, 64);
    seqattn_mma<<<grid, 256, SMEM_TOTAL>>>((const float*)d_in[0], (const float*)d_in[1],
                                           (const float*)d_in[2], (const float*)d_in[3],
                                           (const float*)d_in[4], (float*)d_out);
}

// round 11
// speedup vs baseline: 3.1935x; 1.8441x over previous
#include <cuda_runtime.h>
#include <cuda_bf16.h>
#include <stdint.h>

#define STRB 144              // smem tile row stride, bytes (64 bf16 cols + pad)
#define CEXP 0.06375846855f   // (1/sqrt(512)) * log2(e)
#define RSTR 132              // ring row stride (f32)
#define OSTR 68               // epilogue O-buf row stride (f32)

// smem byte offsets (tiles are 64 rows x 144 B = 9216 B each)
#define T_QH   0
#define T_QL   9216
#define T_KH   18432
#define T_KL   27648
#define T_VH   36864
#define T_VL   46080
#define T_PEH  55296
#define T_PEL  64512
#define T_RING 73728          // ring 64x132 f32; epilogue reuses as 2 O-bufs 64x68
#define T_ZR   108544
#define T_ZM   109056
#define SMEM_TOTAL 109568

typedef uint32_t u32;

// hi parts of two floats as packed bf16x2 (truncation split) — single PRMT
__device__ __forceinline__ u32 hi2(float a, float b) {
    u32 r;
    asm("prmt.b32 %0, %1, %2, 0x7632;"
        : "=r"(r) : "r"(__float_as_uint(a)), "r"(__float_as_uint(b)));
    return r;
}
__device__ __forceinline__ float flo(float x) {
    return x - __int_as_float(__float_as_int(x) & 0xffff0000);
}
__device__ __forceinline__ u32 lo2(float a, float b) {
    __nv_bfloat162 t = __floats2bfloat162_rn(flo(a), flo(b));
    return *reinterpret_cast<u32*>(&t);
}
__device__ __forceinline__ void mma(float* c, const u32* a, const u32* b) {
    asm volatile("mma.sync.aligned.m16n8k16.row.col.f32.bf16.bf16.f32 "
        "{%0,%1,%2,%3}, {%4,%5,%6,%7}, {%8,%9}, {%0,%1,%2,%3};"
        : "+f"(c[0]), "+f"(c[1]), "+f"(c[2]), "+f"(c[3])
        : "r"(a[0]), "r"(a[1]), "r"(a[2]), "r"(a[3]), "r"(b[0]), "r"(b[1]));
}
__device__ __forceinline__ void ldsm4(u32* r, u32 a) {
    asm volatile("ldmatrix.sync.aligned.m8n8.x4.shared.b16 {%0,%1,%2,%3}, [%4];"
        : "=r"(r[0]), "=r"(r[1]), "=r"(r[2]), "=r"(r[3]) : "r"(a));
}
__device__ __forceinline__ void ldsm4t(u32* r, u32 a) {
    asm volatile("ldmatrix.sync.aligned.m8n8.x4.trans.shared.b16 {%0,%1,%2,%3}, [%4];"
        : "=r"(r[0]), "=r"(r[1]), "=r"(r[2]), "=r"(r[3]) : "r"(a));
}
__device__ __forceinline__ u32 smem_u32(const void* p) {
    u32 a;
    asm("{ .reg .u64 t; cvta.to.shared.u64 t, %1; cvt.u32.u64 %0, t; }" : "=r"(a) : "l"(p));
    return a;
}

// 64x64 f32 gmem tile (row stride gs) -> bf16 hi/lo smem tiles, natural layout
__device__ __forceinline__ void cvt_nat(const float* __restrict__ src, int gs,
                                        char* dh, char* dl, int tid) {
    #pragma unroll
    for (int t = 0; t < 4; t++) {
        int idx = tid + t * 256;
        int r = idx >> 4, c4 = (idx & 15) * 4;
        float4 v = *(const float4*)(src + (size_t)r * gs + c4);
        *(uint2*)(dh + r * STRB + c4 * 2) = make_uint2(hi2(v.x, v.y), hi2(v.z, v.w));
        *(uint2*)(dl + r * STRB + c4 * 2) = make_uint2(lo2(v.x, v.y), lo2(v.z, v.w));
    }
}

__global__ __launch_bounds__(256, 2)
void seqattn_mma(const float* __restrict__ q,  const float* __restrict__ kk,
                 const float* __restrict__ vv, const float* __restrict__ pe,
                 const float* __restrict__ cval, float* __restrict__ out)
{
    extern __shared__ char smem[];
    float* ring = (float*)(smem + T_RING);

    const int tid = threadIdx.x;
    const int lane = tid & 31, w = tid >> 5;
    const int g = lane >> 2, tig = lane & 3;
    const int wr = w & 3, wc = w >> 2;
    const int r0 = wr * 16;             // row strip base (block-local)
    const int cb = wc * 32;             // key/col strip base
    const int lr = lane & 7, qd = lane >> 3;   // ldmatrix lane group

    const int bh = blockIdx.y, m0 = blockIdx.x * 64;
    const float cvL  = cval[bh & 7] * 1024.0f;
    const float madd = (cvL - 1023.0f) * 0.03125f + 1.0f;

    const float* qb = q  + (size_t)bh * 1024 * 64;
    const float* kb = kk + (size_t)bh * 2048 * 64;
    const float* vb = vv + (size_t)bh * 2048 * 64;

    const u32 sb = smem_u32(smem);
    // ldmatrix per-lane base addresses (chunk-invariant)
    const u32 baseQh = sb + T_QH + (u32)((r0 + (qd & 1) * 8 + lr) * STRB) + (u32)((qd >> 1) * 16);
    const u32 baseK  = sb + ((qd < 2) ? T_KH  : T_KL)  + (u32)((cb + lr) * STRB) + (u32)((qd & 1) * 16);
    const u32 baseV  = sb + ((qd < 2) ? T_VH  : T_VL)  + (u32)((cb + (qd & 1) * 8 + lr) * STRB);
    const u32 basePE = sb + ((qd < 2) ? T_PEH : T_PEL) + (u32)(((qd & 1) * 8 + lr) * STRB) + (u32)(cb * 2);

    cvt_nat(qb + (size_t)m0 * 64, 64, smem + T_QH, smem + T_QL, tid);
    __syncthreads();

    // Q A-fragments, persist across chunks
    u32 qfh[4][4], qfl[4][4];
    #pragma unroll
    for (int kt = 0; kt < 4; kt++) {
        ldsm4(qfh[kt], baseQh + kt * 32);
        ldsm4(qfl[kt], baseQh + (T_QL - T_QH) + kt * 32);
    }

    float o[8][4];
    #pragma unroll
    for (int i = 0; i < 8; i++) { o[i][0] = o[i][1] = o[i][2] = o[i][3] = 0.f; }
    float zr0 = 0.f, zr1 = 0.f, zm0 = 0.f, zm1 = 0.f;

    #pragma unroll 1
    for (int c = 0; c < 17; c++) {
        const int n0 = m0 + c * 64, l0 = c * 64;

        __syncthreads();   // prev chunk's smem consumers done
        cvt_nat(kb + (size_t)n0 * 64, 64, smem + T_KH, smem + T_KL, tid);
        cvt_nat(vb + (size_t)n0 * 64, 64, smem + T_VH, smem + T_VL, tid);
        if (l0 < 1024) cvt_nat(pe + l0, 1024, smem + T_PEH, smem + T_PEL, tid);
        __syncthreads();   // tiles ready

        float cs[4][4];
        // ---- POS = Q . PE  (PE natural [d][l], transposed by ldsm4t) ----
        if (l0 < 1024) {
            #pragma unroll
            for (int nt = 0; nt < 4; nt++)
                cs[nt][0] = cs[nt][1] = cs[nt][2] = cs[nt][3] = 0.f;
            #pragma unroll
            for (int nt = 0; nt < 4; nt++) {
                #pragma unroll
                for (int kt = 0; kt < 4; kt++) {
                    u32 f[4];
                    ldsm4t(f, basePE + kt * 2304 + nt * 16);
                    mma(cs[nt], qfh[kt], f);
                    mma(cs[nt], qfh[kt], f + 2);
                    mma(cs[nt], qfl[kt], f);
                }
            }
            int slot = (c & 1) * 64;
            #pragma unroll
            for (int nt = 0; nt < 4; nt++) {
                int jl = cb + 8 * nt + tig * 2;
                ring[(r0 + g) * RSTR + slot + jl]         = cs[nt][0];
                ring[(r0 + g) * RSTR + slot + jl + 1]     = cs[nt][1];
                ring[(r0 + g + 8) * RSTR + slot + jl]     = cs[nt][2];
                ring[(r0 + g + 8) * RSTR + slot + jl + 1] = cs[nt][3];
            }
        }

        // ---- S = Q . K^T  (K natural [j][d], non-trans ldsm) ----
        #pragma unroll
        for (int nt = 0; nt < 4; nt++)
            cs[nt][0] = cs[nt][1] = cs[nt][2] = cs[nt][3] = 0.f;
        #pragma unroll
        for (int nt = 0; nt < 4; nt++) {
            #pragma unroll
            for (int kt = 0; kt < 4; kt++) {
                u32 f[4];
                ldsm4(f, baseK + nt * 1152 + kt * 32);
                mma(cs[nt], qfh[kt], f);
                mma(cs[nt], qfh[kt], f + 2);
                mma(cs[nt], qfl[kt], f);
            }
        }
        __syncthreads();   // ring slot c visible to all warps

        // ---- scoring: exp2 poly + span mask, deferred normalization ----
        #pragma unroll
        for (int nt = 0; nt < 4; nt++) {
            #pragma unroll
            for (int e = 0; e < 4; e++) {
                int rr = r0 + g + (e & 2) * 4;
                int j  = cb + 8 * nt + tig * 2 + (e & 1);
                int l  = l0 + j - rr;
                float pos = ring[rr * RSTR + (l & 127)];
                float y = (cs[nt][e] + pos) * CEXP;
                int ni = __float2int_rn(y);
                float f = y - (float)ni;
                float p = fmaf(f, 1.3333558146e-3f, 9.6181291076e-3f);
                p = fmaf(f, p, 5.5504108664e-2f);
                p = fmaf(f, p, 2.4022650696e-1f);
                p = fmaf(f, p, 6.9314718056e-1f);
                p = fmaf(f, p, 1.0f);
                float ev = __int_as_float(__float_as_int(p) + (ni << 23));
                bool ok = ((unsigned)l < 1024u);
                ev = ok ? ev : 0.f;
                float mk = fminf(fmaxf(fmaf((float)l, 0.03125f, madd), 0.f), 1.f);
                float pm = ev * mk;
                if (e & 2) { zr1 += ev; zm1 += pm; }
                else       { zr0 += ev; zm0 += pm; }
                cs[nt][e] = pm;
            }
        }

        // ---- pack P into A-fragments (register-only, FA2 trick) ----
        u32 pfh[2][4], pfl[2][4];
        #pragma unroll
        for (int k2 = 0; k2 < 2; k2++) {
            pfh[k2][0] = hi2(cs[2*k2][0], cs[2*k2][1]);
            pfh[k2][1] = hi2(cs[2*k2][2], cs[2*k2][3]);
            pfh[k2][2] = hi2(cs[2*k2+1][0], cs[2*k2+1][1]);
            pfh[k2][3] = hi2(cs[2*k2+1][2], cs[2*k2+1][3]);
            pfl[k2][0] = lo2(cs[2*k2][0], cs[2*k2][1]);
            pfl[k2][1] = lo2(cs[2*k2][2], cs[2*k2][3]);
            pfl[k2][2] = lo2(cs[2*k2+1][0], cs[2*k2+1][1]);
            pfl[k2][3] = lo2(cs[2*k2+1][0] == cs[2*k2+1][0] ? cs[2*k2+1][2] : 0.f, cs[2*k2+1][3]);
        }
        // fix accidental expression above: recompute cleanly
        #pragma unroll
        for (int k2 = 0; k2 < 2; k2++)
            pfl[k2][3] = lo2(cs[2*k2+1][2], cs[2*k2+1][3]);

        // ---- O += P . V  (V natural [j][d], transposed by ldsm4t) ----
        #pragma unroll
        for (int nt = 0; nt < 8; nt++) {
            #pragma unroll
            for (int k2 = 0; k2 < 2; k2++) {
                u32 f[4];
                ldsm4t(f, baseV + k2 * 2304 + nt * 16);
                mma(o[nt], pfh[k2], f);
                mma(o[nt], pfh[k2], f + 2);
                mma(o[nt], pfl[k2], f);
            }
        }
    }

    // ---------------- epilogue ----------------
    __syncthreads();   // last ring reads done; reuse ring region as O-bufs
    zr0 += __shfl_xor_sync(0xffffffffu, zr0, 1); zr0 += __shfl_xor_sync(0xffffffffu, zr0, 2);
    zr1 += __shfl_xor_sync(0xffffffffu, zr1, 1); zr1 += __shfl_xor_sync(0xffffffffu, zr1, 2);
    zm0 += __shfl_xor_sync(0xffffffffu, zm0, 1); zm0 += __shfl_xor_sync(0xffffffffu, zm0, 2);
    zm1 += __shfl_xor_sync(0xffffffffu, zm1, 1); zm1 += __shfl_xor_sync(0xffffffffu, zm1, 2);
    float* ZR = (float*)(smem + T_ZR);
    float* ZM = (float*)(smem + T_ZM);
    if (tig == 0) {
        ZR[wc * 64 + r0 + g] = zr0;  ZR[wc * 64 + r0 + g + 8] = zr1;
        ZM[wc * 64 + r0 + g] = zm0;  ZM[wc * 64 + r0 + g + 8] = zm1;
    }
    float* Ob = (float*)(smem + T_RING) + wc * (64 * OSTR);
    #pragma unroll
    for (int nt = 0; nt < 8; nt++) {
        int d = 8 * nt + tig * 2;
        Ob[(r0 + g) * OSTR + d]         = o[nt][0];
        Ob[(r0 + g) * OSTR + d + 1]     = o[nt][1];
        Ob[(r0 + g + 8) * OSTR + d]     = o[nt][2];
        Ob[(r0 + g + 8) * OSTR + d + 1] = o[nt][3];
    }
    __syncthreads();
    float* A = (float*)(smem + T_RING);
    float* B = A + 64 * OSTR;
    #pragma unroll
    for (int t = 0; t < 4; t++) {
        int idx = tid + t * 256;
        int r = idx >> 4, d4 = (idx & 15) * 4;
        float inv = 1.f / ((ZM[r] + ZM[64 + r]) + 1e-8f * (ZR[r] + ZR[64 + r]));
        float4 a = *(float4*)&A[r * OSTR + d4];
        float4 b = *(float4*)&B[r * OSTR + d4];
        float4 ov = make_float4((a.x + b.x) * inv, (a.y + b.y) * inv,
                                (a.z + b.z) * inv, (a.w + b.w) * inv);
        *(float4*)&out[((size_t)bh * 1024 + m0 + r) * 64 + d4] = ov;
    }
}

extern "C" void kernel_launch(void* const* d_in, const int* in_sizes, int n_in,
                              void* d_out, int out_size)
{
    (void)in_sizes; (void)n_in; (void)out_size;
    cudaFuncSetAttribute(seqattn_mma, cudaFuncAttributeMaxDynamicSharedMemorySize, SMEM_TOTAL);
    dim3 grid(16, 64);
    seqattn_mma<<<grid, 256, SMEM_TOTAL>>>((const float*)d_in[0], (const float*)d_in[1],
                                           (const float*)d_in[2], (const float*)d_in[3],
                                           (const float*)d_in[4], (float*)d_out);
}